// round 1
// baseline (speedup 1.0000x reference)
#include <cuda_runtime.h>
#include <math.h>
#include <stdint.h>

#define NN 100000
#define EE 800000
#define FD 128   // H * C
#define KD 64    // input dim of each GEMM (IN = HID = 64)
#define EDD 32   // edge attr dim
#define HH 2     // heads

// ---------------- scratch (device globals; no allocation allowed) -----------
__device__ int   g_degi[NN];
__device__ float g_dn1[NN];
__device__ float g_dn2[NN];
__device__ float g_Wq[FD * KD];
__device__ float g_v[HH * EDD];
__device__ float g_h[NN * FD];          // 51.2 MB
__device__ float g_asrc[NN * HH];
__device__ float g_adst[NN * HH];
__device__ float g_alpha[EE * HH];      // 6.4 MB
__device__ float g_m[NN * HH];
__device__ float g_den[NN * HH];
__device__ float g_acc[NN * FD];        // 51.2 MB
__device__ float g_x2[NN * KD];         // 25.6 MB (layer-1 output / pre-quant temp)
__device__ float g_wscale[1];
__device__ int   g_imax[1];

// ---------------- helpers ---------------------------------------------------
__device__ __forceinline__ void atomicMaxF(float* addr, float v) {
    if (v >= 0.f) atomicMax((int*)addr, __float_as_int(v));
    else          atomicMin((unsigned int*)addr, __float_as_uint(v));
}

// ---------------- init / degree ---------------------------------------------
__global__ void k_zero_deg() {
    int i = blockIdx.x * blockDim.x + threadIdx.x;
    if (i < NN) g_degi[i] = 0;
}

__global__ void k_deg(const int* __restrict__ src) {
    int e = blockIdx.x * blockDim.x + threadIdx.x;
    if (e < EE) atomicAdd(&g_degi[src[e]], 1);
}

__global__ void k_dnorm(const float* __restrict__ a1, const float* __restrict__ a2) {
    int n = blockIdx.x * blockDim.x + threadIdx.x;
    if (n < NN) {
        float d = (float)(g_degi[n] + 1);
        g_dn1[n] = powf(d, -a1[0]);
        g_dn2[n] = powf(d, -a2[0]);
    }
}

__global__ void k_reset() {
    int i = blockIdx.x * blockDim.x + threadIdx.x;
    if (i < NN * FD / 4) ((float4*)g_acc)[i] = make_float4(0.f, 0.f, 0.f, 0.f);
    if (i < NN * HH) { g_den[i] = 0.f; g_m[i] = __int_as_float(0xff800000); }
    if (i == 0) g_imax[0] = 0;
}

// ---------------- fake-quant of W -------------------------------------------
__global__ void k_maxabsW(const float* __restrict__ w) {
    __shared__ float sm[256];
    float m = 0.f;
    for (int i = threadIdx.x; i < FD * KD; i += 256) m = fmaxf(m, fabsf(w[i]));
    sm[threadIdx.x] = m;
    __syncthreads();
    for (int s = 128; s > 0; s >>= 1) {
        if (threadIdx.x < s) sm[threadIdx.x] = fmaxf(sm[threadIdx.x], sm[threadIdx.x + s]);
        __syncthreads();
    }
    if (threadIdx.x == 0) g_wscale[0] = fmaxf(sm[0], 1e-8f) / 127.0f;
}

__global__ void k_quantW(const float* __restrict__ w) {
    int i = blockIdx.x * blockDim.x + threadIdx.x;
    if (i < FD * KD) {
        float s = g_wscale[0];
        float q = rintf(w[i] / s);
        q = fminf(fmaxf(q, -128.f), 127.f);
        g_Wq[i] = q * s;
    }
}

// v[h,d] = sum_c att_edge[h,c] * We[(h*64+c), d]   (folds he away entirely)
__global__ void k_vedge(const float* __restrict__ We, const float* __restrict__ ae) {
    int i = threadIdx.x;
    if (i < HH * EDD) {
        int h = i / EDD, d = i % EDD;
        float s = 0.f;
        for (int c = 0; c < 64; c++) s += ae[h * 64 + c] * We[(h * 64 + c) * EDD + d];
        g_v[i] = s;
    }
}

// ---------------- degree-norm + GEMM + attention-coefficient epilogue -------
// g_h[n,o] = (x[n,:]*dn[n]) @ Wq[o,:] ; a_src/a_dst per (n,h)
__global__ __launch_bounds__(256) void k_gemm(const float* __restrict__ xin_or_null,
                                              int layer,
                                              const float* __restrict__ as_g,
                                              const float* __restrict__ ad_g) {
    __shared__ float sW[FD * 65];      // padded: stride 65 kills bank conflicts
    __shared__ float sX[32 * 65];
    __shared__ float sA[32 * 8];
    __shared__ float sD[32 * 8];

    const float* xin = xin_or_null ? xin_or_null : g_x2;
    const float* dn = (layer == 1) ? g_dn1 : g_dn2;

    int t = threadIdx.x;
    int nb = blockIdx.x * 32;

    for (int i = t; i < FD * KD; i += 256) {
        int o = i >> 6, k = i & 63;
        sW[o * 65 + k] = g_Wq[i];
    }
    for (int i = t; i < 32 * KD; i += 256) {
        int nl = i >> 6, k = i & 63;
        int n = nb + nl;
        sX[nl * 65 + k] = (n < NN) ? xin[n * KD + k] * dn[n] : 0.f;
    }
    __syncthreads();

    int nl = t >> 3;            // 32 nodes / block
    int ob = (t & 7) * 16;      // 8 thread-groups x 16 outputs = 128
    float acc[16];
#pragma unroll
    for (int j = 0; j < 16; j++) acc[j] = 0.f;

    for (int k = 0; k < KD; k++) {
        float xv = sX[nl * 65 + k];
#pragma unroll
        for (int j = 0; j < 16; j++) acc[j] += xv * sW[(ob + j) * 65 + k];
    }

    float ps = 0.f, pd = 0.f;
    int n = nb + nl;
    if (n < NN) {
#pragma unroll
        for (int j = 0; j < 16; j += 4) {
            float4 vv = make_float4(acc[j], acc[j + 1], acc[j + 2], acc[j + 3]);
            *((float4*)&g_h[n * FD + ob + j]) = vv;
        }
#pragma unroll
        for (int j = 0; j < 16; j++) {
            ps += acc[j] * as_g[ob + j];
            pd += acc[j] * ad_g[ob + j];
        }
    }
    sA[nl * 8 + (t & 7)] = ps;
    sD[nl * 8 + (t & 7)] = pd;
    __syncthreads();

    if (t < 64) {
        int nl2 = t >> 1, h = t & 1;
        int base = nl2 * 8 + h * 4;
        float s = sA[base] + sA[base + 1] + sA[base + 2] + sA[base + 3];
        float d = sD[base] + sD[base + 1] + sD[base + 2] + sD[base + 3];
        int n2 = nb + nl2;
        if (n2 < NN) { g_asrc[n2 * 2 + h] = s; g_adst[n2 * 2 + h] = d; }
    }
}

// ---------------- edge pass 1: alpha + leaky-ReLU + segment max -------------
__global__ void k_alpha(const int* __restrict__ src, const int* __restrict__ dst,
                        const float* __restrict__ ea) {
    __shared__ float sv[HH * EDD];
    if (threadIdx.x < HH * EDD) sv[threadIdx.x] = g_v[threadIdx.x];
    __syncthreads();
    int e = blockIdx.x * blockDim.x + threadIdx.x;
    if (e >= EE) return;

    const float4* p = (const float4*)(ea + (size_t)e * EDD);
    float a0 = 0.f, a1 = 0.f;
#pragma unroll
    for (int i = 0; i < 8; i++) {
        float4 q = p[i];
        a0 += q.x * sv[i * 4] + q.y * sv[i * 4 + 1] + q.z * sv[i * 4 + 2] + q.w * sv[i * 4 + 3];
        a1 += q.x * sv[32 + i * 4] + q.y * sv[32 + i * 4 + 1] + q.z * sv[32 + i * 4 + 2] + q.w * sv[32 + i * 4 + 3];
    }
    int s = src[e], d = dst[e];
    float al0 = g_asrc[s * 2]     + g_adst[d * 2]     + a0;
    float al1 = g_asrc[s * 2 + 1] + g_adst[d * 2 + 1] + a1;
    al0 = (al0 >= 0.f) ? al0 : 0.2f * al0;
    al1 = (al1 >= 0.f) ? al1 : 0.2f * al1;
    ((float2*)g_alpha)[e] = make_float2(al0, al1);
    atomicMaxF(&g_m[d * 2],     al0);
    atomicMaxF(&g_m[d * 2 + 1], al1);
}

// ---------------- edge pass 2: exp + segment sum ----------------------------
__global__ void k_exp(const int* __restrict__ dst) {
    int e = blockIdx.x * blockDim.x + threadIdx.x;
    if (e >= EE) return;
    int d = dst[e];
    float2 al = ((const float2*)g_alpha)[e];
    float2 m = ((const float2*)g_m)[d];
    float e0 = __expf(al.x - m.x);
    float e1 = __expf(al.y - m.y);
    ((float2*)g_alpha)[e] = make_float2(e0, e1);
    atomicAdd(&g_den[d * 2],     e0);
    atomicAdd(&g_den[d * 2 + 1], e1);
}

// ---------------- edge pass 3: weighted gather/scatter (warp per edge) ------
__global__ __launch_bounds__(256) void k_scatter(const int* __restrict__ src,
                                                 const int* __restrict__ dst) {
    int gw = (blockIdx.x * blockDim.x + threadIdx.x) >> 5;
    int lane = threadIdx.x & 31;
    if (gw >= EE) return;
    int s = src[gw], d = dst[gw];
    float2 ev  = ((const float2*)g_alpha)[gw];
    float2 den = ((const float2*)g_den)[d];
    float w0 = ev.x / (den.x + 1e-16f);
    float w1 = ev.y / (den.y + 1e-16f);
    float w = (lane < 16) ? w0 : w1;     // lanes 0-15: head 0 (c 0..63)
    float4 hv = ((const float4*)(g_h + (size_t)s * FD))[lane];
    float* out = g_acc + (size_t)d * FD + lane * 4;
    asm volatile("red.global.add.v4.f32 [%0], {%1,%2,%3,%4};"
                 :: "l"(out), "f"(hv.x * w), "f"(hv.y * w), "f"(hv.z * w), "f"(hv.w * w)
                 : "memory");
}

// ---------------- head mean + bias, then per-tensor fake-quant --------------
__global__ void k_fin_pre(const float* __restrict__ bias) {
    int i = blockIdx.x * blockDim.x + threadIdx.x;
    float mv = 0.f;
    if (i < NN * KD) {
        int n = i >> 6, c = i & 63;
        float t = (g_acc[n * FD + c] + g_acc[n * FD + 64 + c]) * 0.5f + bias[c];
        g_x2[i] = t;
        mv = fabsf(t);
    }
#pragma unroll
    for (int o = 16; o; o >>= 1) mv = fmaxf(mv, __shfl_xor_sync(0xffffffffu, mv, o));
    __shared__ float sm[8];
    if ((threadIdx.x & 31) == 0) sm[threadIdx.x >> 5] = mv;
    __syncthreads();
    if (threadIdx.x < 8) {
        float v = sm[threadIdx.x];
#pragma unroll
        for (int o = 4; o; o >>= 1) v = fmaxf(v, __shfl_xor_sync(0xffu, v, o));
        if (threadIdx.x == 0) atomicMax(&g_imax[0], __float_as_int(v));
    }
}

__global__ void k_fin_post(float* __restrict__ out, int relu) {
    int i = blockIdx.x * blockDim.x + threadIdx.x;
    if (i >= NN * KD) return;
    float s = fmaxf(__int_as_float(g_imax[0]), 1e-8f) * (1.f / 127.f);
    float q = rintf(g_x2[i] / s);
    q = fminf(fmaxf(q, -128.f), 127.f) * s;
    if (relu) q = fmaxf(q, 0.f);
    if (out) out[i] = q;
    else     g_x2[i] = q;
}

// ---------------- host ------------------------------------------------------
extern "C" void kernel_launch(void* const* d_in, const int* in_sizes, int n_in,
                              void* d_out, int out_size) {
    const float* x    = (const float*)d_in[0];
    const int*   ei   = (const int*)d_in[1];
    const int*   src  = ei;
    const int*   dst  = ei + EE;
    const float* ea   = (const float*)d_in[2];
    const float* a1   = (const float*)d_in[3];
    const float* W1   = (const float*)d_in[4];
    const float* We1  = (const float*)d_in[5];
    const float* as1  = (const float*)d_in[6];
    const float* ad1  = (const float*)d_in[7];
    const float* ae1  = (const float*)d_in[8];
    const float* b1   = (const float*)d_in[9];
    const float* a2   = (const float*)d_in[10];
    const float* W2   = (const float*)d_in[11];
    const float* We2  = (const float*)d_in[12];
    const float* as2  = (const float*)d_in[13];
    const float* ad2  = (const float*)d_in[14];
    const float* ae2  = (const float*)d_in[15];
    const float* b2   = (const float*)d_in[16];
    float* out = (float*)d_out;

    const int TB = 256;
    int gN   = (NN + TB - 1) / TB;
    int gE   = (EE + TB - 1) / TB;
    int gRst = (NN * FD / 4 + TB - 1) / TB;
    int gW   = (FD * KD + TB - 1) / TB;
    int gGem = (NN + 31) / 32;
    int gSct = (EE * 32 + TB - 1) / TB;
    int gF   = (NN * KD + TB - 1) / TB;

    // degree + norms (shared across both layers)
    k_zero_deg<<<gN, TB>>>();
    k_deg<<<gE, TB>>>(src);
    k_dnorm<<<gN, TB>>>(a1, a2);

    // ---- layer 1 ----
    k_reset<<<gRst, TB>>>();
    k_maxabsW<<<1, 256>>>(W1);
    k_quantW<<<gW, TB>>>(W1);
    k_vedge<<<1, 64>>>(We1, ae1);
    k_gemm<<<gGem, 256>>>(x, 1, as1, ad1);
    k_alpha<<<gE, TB>>>(src, dst, ea);
    k_exp<<<gE, TB>>>(dst);
    k_scatter<<<gSct, TB>>>(src, dst);
    k_fin_pre<<<gF, TB>>>(b1);
    k_fin_post<<<gF, TB>>>(nullptr, 1);   // quant + relu -> g_x2

    // ---- layer 2 ----
    k_reset<<<gRst, TB>>>();
    k_maxabsW<<<1, 256>>>(W2);
    k_quantW<<<gW, TB>>>(W2);
    k_vedge<<<1, 64>>>(We2, ae2);
    k_gemm<<<gGem, 256>>>(nullptr, 2, as2, ad2);  // reads g_x2
    k_alpha<<<gE, TB>>>(src, dst, ea);
    k_exp<<<gE, TB>>>(dst);
    k_scatter<<<gSct, TB>>>(src, dst);
    k_fin_pre<<<gF, TB>>>(b2);
    k_fin_post<<<gF, TB>>>(out, 0);       // final quant -> d_out
}

// round 3
// speedup vs baseline: 1.1508x; 1.1508x over previous
#include <cuda_runtime.h>
#include <math.h>
#include <stdint.h>

#define NN 100000
#define EE 800000
#define FD 128   // H * C
#define KD 64    // input dim of each GEMM (IN = HID = 64)
#define EDD 32   // edge attr dim
#define HH 2     // heads

// ---------------- scratch (device globals) -----------------------------------
__device__ int   g_degi[NN];
__device__ float g_dn1[NN];
__device__ float g_dn2[NN];
__device__ float g_Wq[FD * KD];
__device__ float g_v1[HH * EDD];
__device__ float g_v2[HH * EDD];
__device__ float g_ae1[EE * HH];        // 6.4 MB  per-edge a_edge, layer 1
__device__ float g_ae2[EE * HH];        // 6.4 MB  per-edge a_edge, layer 2
__device__ float g_h[NN * FD];          // 51.2 MB
__device__ float g_asrc[NN * HH];
__device__ float g_adst[NN * HH];
__device__ float g_alpha[EE * HH];      // 6.4 MB  (holds exp(alpha))
__device__ float g_den[NN * HH];
__device__ float g_acc[NN * KD];        // 25.6 MB (heads pre-summed)
__device__ float g_x2[NN * KD];         // 25.6 MB
__device__ float g_wscale[1];
__device__ int   g_imax[1];

// ---------------- init / degree ---------------------------------------------
__global__ void k_zero_deg() {
    int i = blockIdx.x * blockDim.x + threadIdx.x;
    if (i < NN) g_degi[i] = 0;
}

__global__ void k_deg(const int* __restrict__ src) {
    int e = blockIdx.x * blockDim.x + threadIdx.x;
    if (e < EE) atomicAdd(&g_degi[src[e]], 1);
}

__global__ void k_dnorm(const float* __restrict__ a1, const float* __restrict__ a2) {
    int n = blockIdx.x * blockDim.x + threadIdx.x;
    if (n < NN) {
        float d = (float)(g_degi[n] + 1);
        g_dn1[n] = powf(d, -a1[0]);
        g_dn2[n] = powf(d, -a2[0]);
    }
}

__global__ void k_reset() {
    int i = blockIdx.x * blockDim.x + threadIdx.x;
    if (i < NN * KD / 4) ((float4*)g_acc)[i] = make_float4(0.f, 0.f, 0.f, 0.f);
    if (i < NN * HH) g_den[i] = 0.f;
    if (i == 0) g_imax[0] = 0;
}

// ---------------- fake-quant of W -------------------------------------------
__global__ void k_maxabsW(const float* __restrict__ w) {
    __shared__ float sm[256];
    float m = 0.f;
    for (int i = threadIdx.x; i < FD * KD; i += 256) m = fmaxf(m, fabsf(w[i]));
    sm[threadIdx.x] = m;
    __syncthreads();
    for (int s = 128; s > 0; s >>= 1) {
        if (threadIdx.x < s) sm[threadIdx.x] = fmaxf(sm[threadIdx.x], sm[threadIdx.x + s]);
        __syncthreads();
    }
    if (threadIdx.x == 0) g_wscale[0] = fmaxf(sm[0], 1e-8f) / 127.0f;
}

__global__ void k_quantW(const float* __restrict__ w) {
    int i = blockIdx.x * blockDim.x + threadIdx.x;
    if (i < FD * KD) {
        float s = g_wscale[0];
        float q = rintf(w[i] / s);
        q = fminf(fmaxf(q, -128.f), 127.f);
        g_Wq[i] = q * s;
    }
}

// v[h,d] = sum_c att_edge[h,c] * We[(h*64+c), d]  -- BOTH layers, one launch.
// (device globals written inside device code only; never passed from host)
__global__ void k_vedge(const float* __restrict__ We1, const float* __restrict__ ae1,
                        const float* __restrict__ We2, const float* __restrict__ ae2) {
    int i = threadIdx.x;
    if (i < HH * EDD) {
        int h = i / EDD, d = i % EDD;
        float s1 = 0.f, s2 = 0.f;
        for (int c = 0; c < 64; c++) {
            s1 += ae1[h * 64 + c] * We1[(h * 64 + c) * EDD + d];
            s2 += ae2[h * 64 + c] * We2[(h * 64 + c) * EDD + d];
        }
        g_v1[i] = s1;
        g_v2[i] = s2;
    }
}

// one pass over edge_attr computing a_edge for BOTH layers
__global__ void k_edgepre(const float* __restrict__ ea) {
    __shared__ float sv1[HH * EDD];
    __shared__ float sv2[HH * EDD];
    if (threadIdx.x < HH * EDD) { sv1[threadIdx.x] = g_v1[threadIdx.x]; sv2[threadIdx.x] = g_v2[threadIdx.x]; }
    __syncthreads();
    int e = blockIdx.x * blockDim.x + threadIdx.x;
    if (e >= EE) return;
    const float4* p = (const float4*)(ea + (size_t)e * EDD);
    float a0 = 0.f, a1 = 0.f, b0 = 0.f, b1 = 0.f;
#pragma unroll
    for (int i = 0; i < 8; i++) {
        float4 q = p[i];
        a0 += q.x * sv1[i*4] + q.y * sv1[i*4+1] + q.z * sv1[i*4+2] + q.w * sv1[i*4+3];
        a1 += q.x * sv1[32+i*4] + q.y * sv1[32+i*4+1] + q.z * sv1[32+i*4+2] + q.w * sv1[32+i*4+3];
        b0 += q.x * sv2[i*4] + q.y * sv2[i*4+1] + q.z * sv2[i*4+2] + q.w * sv2[i*4+3];
        b1 += q.x * sv2[32+i*4] + q.y * sv2[32+i*4+1] + q.z * sv2[32+i*4+2] + q.w * sv2[32+i*4+3];
    }
    ((float2*)g_ae1)[e] = make_float2(a0, a1);
    ((float2*)g_ae2)[e] = make_float2(b0, b1);
}

// ---------------- degree-norm + GEMM + attention-coefficient epilogue -------
__global__ __launch_bounds__(256) void k_gemm(const float* __restrict__ xin_or_null,
                                              int layer,
                                              const float* __restrict__ as_g,
                                              const float* __restrict__ ad_g) {
    __shared__ float sW[FD * 65];
    __shared__ float sX[32 * 65];
    __shared__ float sA[32 * 8];
    __shared__ float sD[32 * 8];

    const float* xin = xin_or_null ? xin_or_null : g_x2;
    const float* dn = (layer == 1) ? g_dn1 : g_dn2;

    int t = threadIdx.x;
    int nb = blockIdx.x * 32;

    for (int i = t; i < FD * KD; i += 256) {
        int o = i >> 6, k = i & 63;
        sW[o * 65 + k] = g_Wq[i];
    }
    for (int i = t; i < 32 * KD; i += 256) {
        int nl = i >> 6, k = i & 63;
        int n = nb + nl;
        sX[nl * 65 + k] = (n < NN) ? xin[n * KD + k] * dn[n] : 0.f;
    }
    __syncthreads();

    int nl = t >> 3;
    int ob = (t & 7) * 16;
    float acc[16];
#pragma unroll
    for (int j = 0; j < 16; j++) acc[j] = 0.f;

    for (int k = 0; k < KD; k++) {
        float xv = sX[nl * 65 + k];
#pragma unroll
        for (int j = 0; j < 16; j++) acc[j] += xv * sW[(ob + j) * 65 + k];
    }

    float ps = 0.f, pd = 0.f;
    int n = nb + nl;
    if (n < NN) {
#pragma unroll
        for (int j = 0; j < 16; j += 4) {
            float4 vv = make_float4(acc[j], acc[j+1], acc[j+2], acc[j+3]);
            *((float4*)&g_h[n * FD + ob + j]) = vv;
        }
#pragma unroll
        for (int j = 0; j < 16; j++) {
            ps += acc[j] * as_g[ob + j];
            pd += acc[j] * ad_g[ob + j];
        }
    }
    sA[nl * 8 + (t & 7)] = ps;
    sD[nl * 8 + (t & 7)] = pd;
    __syncthreads();

    if (t < 64) {
        int nl2 = t >> 1, h = t & 1;
        int base = nl2 * 8 + h * 4;
        float s = sA[base] + sA[base+1] + sA[base+2] + sA[base+3];
        float d = sD[base] + sD[base+1] + sD[base+2] + sD[base+3];
        int n2 = nb + nl2;
        if (n2 < NN) { g_asrc[n2*2+h] = s; g_adst[n2*2+h] = d; }
    }
}

// ---------------- fused edge pass: alpha + leaky + exp + denom sum ----------
// (segment-max removed: softmax is shift-invariant and alpha is O(1))
__global__ void k_alpha(const int* __restrict__ src, const int* __restrict__ dst,
                        int layer) {
    const float2* ae_stored = (layer == 1) ? (const float2*)g_ae1 : (const float2*)g_ae2;
    int e = blockIdx.x * blockDim.x + threadIdx.x;
    if (e >= EE) return;
    int s = src[e], d = dst[e];
    float2 aev = ae_stored[e];
    float2 as = ((const float2*)g_asrc)[s];
    float2 ad = ((const float2*)g_adst)[d];
    float al0 = as.x + ad.x + aev.x;
    float al1 = as.y + ad.y + aev.y;
    al0 = (al0 >= 0.f) ? al0 : 0.2f * al0;
    al1 = (al1 >= 0.f) ? al1 : 0.2f * al1;
    float e0 = __expf(al0);
    float e1 = __expf(al1);
    ((float2*)g_alpha)[e] = make_float2(e0, e1);
    float* dp = g_den + d * 2;
    asm volatile("red.global.add.v2.f32 [%0], {%1,%2};"
                 :: "l"(dp), "f"(e0), "f"(e1) : "memory");
}

// ---------------- edge scatter: heads combined, half-warp per edge ----------
__global__ __launch_bounds__(256) void k_scatter(const int* __restrict__ src,
                                                 const int* __restrict__ dst) {
    int idx = blockIdx.x * blockDim.x + threadIdx.x;
    int e = idx >> 4;
    int lane = idx & 15;
    if (e >= EE) return;
    int s = src[e], d = dst[e];
    float2 ev  = ((const float2*)g_alpha)[e];
    float2 den = ((const float2*)g_den)[d];
    float w0 = ev.x / (den.x + 1e-16f);
    float w1 = ev.y / (den.y + 1e-16f);
    const float4* hp = (const float4*)(g_h + (size_t)s * FD);
    float4 a = hp[lane];        // head 0, cols lane*4..
    float4 b = hp[16 + lane];   // head 1
    float4 r = make_float4(w0*a.x + w1*b.x, w0*a.y + w1*b.y,
                           w0*a.z + w1*b.z, w0*a.w + w1*b.w);
    float* out = g_acc + (size_t)d * KD + lane * 4;
    asm volatile("red.global.add.v4.f32 [%0], {%1,%2,%3,%4};"
                 :: "l"(out), "f"(r.x), "f"(r.y), "f"(r.z), "f"(r.w)
                 : "memory");
}

// ---------------- head mean + bias, then per-tensor fake-quant --------------
__global__ void k_fin_pre(const float* __restrict__ bias) {
    int i = blockIdx.x * blockDim.x + threadIdx.x;
    float mv = 0.f;
    if (i < NN * KD) {
        float t = g_acc[i] * 0.5f + bias[i & 63];
        g_x2[i] = t;
        mv = fabsf(t);
    }
#pragma unroll
    for (int o = 16; o; o >>= 1) mv = fmaxf(mv, __shfl_xor_sync(0xffffffffu, mv, o));
    __shared__ float sm[8];
    if ((threadIdx.x & 31) == 0) sm[threadIdx.x >> 5] = mv;
    __syncthreads();
    if (threadIdx.x < 8) {
        float v = sm[threadIdx.x];
#pragma unroll
        for (int o = 4; o; o >>= 1) v = fmaxf(v, __shfl_xor_sync(0xffu, v, o));
        if (threadIdx.x == 0) atomicMax(&g_imax[0], __float_as_int(v));
    }
}

__global__ void k_fin_post(float* __restrict__ out, int relu) {
    int i = blockIdx.x * blockDim.x + threadIdx.x;
    if (i >= NN * KD) return;
    float s = fmaxf(__int_as_float(g_imax[0]), 1e-8f) * (1.f / 127.f);
    float q = rintf(g_x2[i] / s);
    q = fminf(fmaxf(q, -128.f), 127.f) * s;
    if (relu) q = fmaxf(q, 0.f);
    if (out) out[i] = q;
    else     g_x2[i] = q;
}

// ---------------- host ------------------------------------------------------
extern "C" void kernel_launch(void* const* d_in, const int* in_sizes, int n_in,
                              void* d_out, int out_size) {
    const float* x    = (const float*)d_in[0];
    const int*   ei   = (const int*)d_in[1];
    const int*   src  = ei;
    const int*   dst  = ei + EE;
    const float* ea   = (const float*)d_in[2];
    const float* a1   = (const float*)d_in[3];
    const float* W1   = (const float*)d_in[4];
    const float* We1  = (const float*)d_in[5];
    const float* as1  = (const float*)d_in[6];
    const float* ad1  = (const float*)d_in[7];
    const float* ae1  = (const float*)d_in[8];
    const float* b1   = (const float*)d_in[9];
    const float* a2   = (const float*)d_in[10];
    const float* W2   = (const float*)d_in[11];
    const float* We2  = (const float*)d_in[12];
    const float* as2  = (const float*)d_in[13];
    const float* ad2  = (const float*)d_in[14];
    const float* ae2  = (const float*)d_in[15];
    const float* b2   = (const float*)d_in[16];
    float* out = (float*)d_out;

    const int TB = 256;
    int gN   = (NN + TB - 1) / TB;
    int gE   = (EE + TB - 1) / TB;
    int gRst = (NN * KD / 4 + TB - 1) / TB;
    int gW   = (FD * KD + TB - 1) / TB;
    int gGem = (NN + 31) / 32;
    int gSct = (EE * 16 + TB - 1) / TB;
    int gF   = (NN * KD + TB - 1) / TB;

    // shared precompute
    k_zero_deg<<<gN, TB>>>();
    k_deg<<<gE, TB>>>(src);
    k_dnorm<<<gN, TB>>>(a1, a2);
    k_vedge<<<1, 64>>>(We1, ae1, We2, ae2);
    k_edgepre<<<gE, TB>>>(ea);

    // ---- layer 1 ----
    k_reset<<<gRst, TB>>>();
    k_maxabsW<<<1, 256>>>(W1);
    k_quantW<<<gW, TB>>>(W1);
    k_gemm<<<gGem, 256>>>(x, 1, as1, ad1);
    k_alpha<<<gE, TB>>>(src, dst, 1);
    k_scatter<<<gSct, TB>>>(src, dst);
    k_fin_pre<<<gF, TB>>>(b1);
    k_fin_post<<<gF, TB>>>(nullptr, 1);

    // ---- layer 2 ----
    k_reset<<<gRst, TB>>>();
    k_maxabsW<<<1, 256>>>(W2);
    k_quantW<<<gW, TB>>>(W2);
    k_gemm<<<gGem, 256>>>(nullptr, 2, as2, ad2);
    k_alpha<<<gE, TB>>>(src, dst, 2);
    k_scatter<<<gSct, TB>>>(src, dst);
    k_fin_pre<<<gF, TB>>>(b2);
    k_fin_post<<<gF, TB>>>(out, 0);
}